// round 2
// baseline (speedup 1.0000x reference)
#include <cuda_runtime.h>

// Problem dims (fixed per reference setup_inputs)
constexpr int Bb = 32, Cc = 128, Hh = 36, Ww = 100;
constexpr int NELEM = Bb * Cc * Hh * Ww;          // 14,745,600 floats
constexpr int KW = 9;                              // conv taps
constexpr int WSZ = 128 * 9 * 32;                  // per-CTA weight slice in smem (floats)

// Scratch for transposed layout [B][C][W][H] — static device array (no alloc)
__device__ float g_scratch[NELEM];

// ---------------------------------------------------------------------------
// Copy x -> d_out (vectorized)
// ---------------------------------------------------------------------------
__global__ void copy_k(const float4* __restrict__ in, float4* __restrict__ out, int n4) {
    for (int i = blockIdx.x * blockDim.x + threadIdx.x; i < n4; i += gridDim.x * blockDim.x)
        out[i] = in[i];
}

// ---------------------------------------------------------------------------
// Transpose per (b,c) plane: [36][100] -> [100][36] into g_scratch
// ---------------------------------------------------------------------------
__global__ void transpose_HW_to_WH(const float* __restrict__ in) {
    __shared__ float tile[36][101];
    const float* ip = in + (size_t)blockIdx.x * 3600;
    float* op = g_scratch + (size_t)blockIdx.x * 3600;
    for (int idx = threadIdx.x; idx < 3600; idx += blockDim.x) {
        int r = idx / 100, c = idx - r * 100;       // in [36][100]
        tile[r][c] = ip[idx];
    }
    __syncthreads();
    for (int idx = threadIdx.x; idx < 3600; idx += blockDim.x) {
        int c = idx / 36, r = idx - c * 36;         // out [100][36]: idx = w*36 + h
        op[idx] = tile[r][c];
    }
}

// Transpose back: g_scratch [100][36] -> d_out [36][100]
__global__ void transpose_WH_to_HW(float* __restrict__ out) {
    __shared__ float tile[100][37];
    const float* ip = g_scratch + (size_t)blockIdx.x * 3600;
    float* op = out + (size_t)blockIdx.x * 3600;
    for (int idx = threadIdx.x; idx < 3600; idx += blockDim.x) {
        int r = idx / 36, c = idx - r * 36;         // in [100][36]
        tile[r][c] = ip[idx];
    }
    __syncthreads();
    for (int idx = threadIdx.x; idx < 3600; idx += blockDim.x) {
        int c = idx / 100, r = idx - c * 100;       // out [36][100]: idx = h*100 + w
        op[idx] = tile[r][c];                       // = in[w][h]
    }
}

// ---------------------------------------------------------------------------
// One forward + one backward scan pass, in place, on a [B][C][S][L] buffer.
// Cluster of 4 CTAs per batch; CTA `rank` owns output channels [rank*32, rank*32+32).
//   S = scan length (rows), L = conv length per row, T = w-positions per warp.
// SCR selects g_scratch as the working buffer (horizontal passes).
// out[row i] = x[i] + relu( sum_{ci,k} w[co,ci,k] * prev[ci, l+k-4] )
// ---------------------------------------------------------------------------
template <int S, int L, int T, bool SCR>
__global__ void __launch_bounds__(256, 1) __cluster_dims__(4, 1, 1)
pass_pair(float* __restrict__ Yext, const float* __restrict__ wA, const float* __restrict__ wB) {
    constexpr int PROW = 8 * T + 8;   // padded prev-row length (>= L + 8)
    constexpr int SL   = L + 1;       // sout stride (coprime with 32)

    extern __shared__ float sm[];
    float* wsm  = sm;                 // [128ci][9k][32co]
    float* pp   = sm + WSZ;           // [128ci][PROW] padded prev row
    float* sout = pp + 128 * PROW;    // [32co][SL] relu(conv) staging

    float* Y = SCR ? g_scratch : Yext;

    const int tid    = threadIdx.x;
    const int lane   = tid & 31;
    const int warp   = tid >> 5;
    const int rank   = blockIdx.x & 3;
    const int batch  = blockIdx.x >> 2;
    const int coBase = rank * 32;
    float* Yb = Y + (size_t)batch * Cc * S * L;

#pragma unroll 1
    for (int pass = 0; pass < 2; ++pass) {
        const float* wg = pass ? wB : wA;
        // Load this pass's weight slice: w[coBase+c][ci][k] -> wsm[ci*288 + k*32 + c]
        // (global reads coalesced along r; smem scatter is cheap: 144 iters)
        for (int idx = tid; idx < WSZ; idx += 256) {
            int c  = idx / 1152;
            int r  = idx - c * 1152;        // r = ci*9 + k
            int ci = r / 9;
            int k  = r - ci * 9;
            wsm[ci * 288 + k * 32 + c] = wg[(size_t)(coBase + c) * 1152 + r];
        }

#pragma unroll 1
        for (int i = 1; i < S; ++i) {
            const int cur  = pass ? (S - 1 - i) : i;
            const int prev = pass ? (S - i)     : (i - 1);

            // Make our previous-row writes visible, then sync the cluster so
            // every CTA's slice of row `prev` is complete before we read it.
            __threadfence();
            asm volatile("barrier.cluster.arrive.aligned;" ::: "memory");
            asm volatile("barrier.cluster.wait.aligned;" ::: "memory");

            // Stage full prev row (all 128 channels, zero-padded) into smem.
            // __ldcg: bypass L1 — peers wrote these via L2.
            for (int idx = tid; idx < 128 * PROW; idx += 256) {
                int ci = idx / PROW;
                int j  = idx - ci * PROW;
                int l  = j - 4;
                float v = 0.f;
                if (l >= 0 && l < L)
                    v = __ldcg(Yb + ((size_t)ci * S + prev) * L + l);
                pp[idx] = v;
            }
            __syncthreads();   // pp + wsm ready

            // Compute: lane = co, warp = strip of T output positions.
            {
                const int l0 = warp * T;
                float acc[T];
#pragma unroll
                for (int t = 0; t < T; ++t) acc[t] = 0.f;

                for (int ci = 0; ci < 128; ++ci) {
                    const float* ppc = pp + ci * PROW + l0;
                    float pv[T + 8];
#pragma unroll
                    for (int j = 0; j < T + 8; ++j) pv[j] = ppc[j];   // uniform broadcast LDS
                    const float* wrow = wsm + ci * 288 + lane;
#pragma unroll
                    for (int k = 0; k < KW; ++k) {
                        float wk = wrow[k * 32];                      // conflict-free LDS
#pragma unroll
                        for (int t = 0; t < T; ++t)
                            acc[t] = fmaf(wk, pv[t + k], acc[t]);
                    }
                }
#pragma unroll
                for (int t = 0; t < T; ++t) {
                    int l = l0 + t;
                    if (l < L) sout[lane * SL + l] = fmaxf(acc[t], 0.f);
                }
            }
            __syncthreads();   // sout ready

            // In-place: Y[cur] += relu(conv). Coalesced RMW over own channels.
            for (int idx = tid; idx < 32 * L; idx += 256) {
                int c = idx / L;
                int l = idx - c * L;
                float* g = Yb + ((size_t)(coBase + c) * S + cur) * L + l;
                *g = *g + sout[c * SL + l];
            }
            // next iteration's threadfence + cluster barrier orders these writes
        }
        __threadfence();
    }
}

// ---------------------------------------------------------------------------
// Launch
// ---------------------------------------------------------------------------
extern "C" void kernel_launch(void* const* d_in, const int* in_sizes, int n_in,
                              void* d_out, int out_size) {
    const float* x    = (const float*)d_in[0];
    const float* w_ud = (const float*)d_in[1];
    const float* w_du = (const float*)d_in[2];
    const float* w_lr = (const float*)d_in[3];
    const float* w_rl = (const float*)d_in[4];
    float* Y = (float*)d_out;

    // Vertical: S=H=36, L=W=100, T=13.  Horizontal: S=W=100, L=H=36, T=5.
    constexpr int SMEM_V = (WSZ + 128 * (8 * 13 + 8) + 32 * 101) * 4;  // 217,728 B
    constexpr int SMEM_H = (WSZ + 128 * (8 * 5 + 8) + 32 * 37) * 4;    // 176,768 B

    cudaFuncSetAttribute(pass_pair<36, 100, 13, false>,
                         cudaFuncAttributeMaxDynamicSharedMemorySize, SMEM_V);
    cudaFuncSetAttribute(pass_pair<100, 36, 5, true>,
                         cudaFuncAttributeMaxDynamicSharedMemorySize, SMEM_H);

    copy_k<<<2048, 256>>>((const float4*)x, (float4*)Y, NELEM / 4);

    // Pass 1 (ud, forward over H) + Pass 2 (du, backward over H), in place on Y
    pass_pair<36, 100, 13, false><<<128, 256, SMEM_V>>>(Y, w_ud, w_du);

    // Transpose [B][C][H][W] -> [B][C][W][H] so the horizontal conv axis is contiguous
    transpose_HW_to_WH<<<Bb * Cc, 256>>>(Y);

    // Pass 3 (lr, forward over W) + Pass 4 (rl, backward over W), on g_scratch
    pass_pair<100, 36, 5, true><<<128, 256, SMEM_H>>>(nullptr, w_lr, w_rl);

    // Transpose back into d_out
    transpose_WH_to_HW<<<Bb * Cc, 256>>>(Y);
}

// round 3
// speedup vs baseline: 1.3183x; 1.3183x over previous
#include <cuda_runtime.h>

// Problem dims (fixed per reference setup_inputs)
constexpr int Bb = 32, Cc = 128, Hh = 36, Ww = 100;
constexpr int NELEM = Bb * Cc * Hh * Ww;          // 14,745,600 floats
constexpr int KW = 9;

typedef unsigned long long u64;

// fma.rn.f32x2: two independent fp32 FMAs in one instruction (sm_100+)
#define FMA2(d, a, b) asm volatile("fma.rn.f32x2 %0, %1, %2, %0;" : "+l"(d) : "l"(a), "l"(b))

__device__ __forceinline__ float f32x2_sum(u64 v) {
    unsigned lo, hi;
    asm("mov.b64 {%0,%1}, %2;" : "=r"(lo), "=r"(hi) : "l"(v));
    return __uint_as_float(lo) + __uint_as_float(hi);
}

// Scratch for transposed layout [B][C][W][H] — static device array (no alloc)
__device__ float g_scratch[NELEM];

// ---------------------------------------------------------------------------
__global__ void copy_k(const float4* __restrict__ in, float4* __restrict__ out, int n4) {
    for (int i = blockIdx.x * blockDim.x + threadIdx.x; i < n4; i += gridDim.x * blockDim.x)
        out[i] = in[i];
}

// Transpose per (b,c) plane: [36][100] -> [100][36] into g_scratch
__global__ void transpose_HW_to_WH(const float* __restrict__ in) {
    __shared__ float tile[36][101];
    const float* ip = in + (size_t)blockIdx.x * 3600;
    float* op = g_scratch + (size_t)blockIdx.x * 3600;
    for (int idx = threadIdx.x; idx < 3600; idx += blockDim.x) {
        int r = idx / 100, c = idx - r * 100;
        tile[r][c] = ip[idx];
    }
    __syncthreads();
    for (int idx = threadIdx.x; idx < 3600; idx += blockDim.x) {
        int c = idx / 36, r = idx - c * 36;
        op[idx] = tile[r][c];
    }
}

// Transpose back: g_scratch [100][36] -> d_out [36][100]
__global__ void transpose_WH_to_HW(float* __restrict__ out) {
    __shared__ float tile[100][37];
    const float* ip = g_scratch + (size_t)blockIdx.x * 3600;
    float* op = out + (size_t)blockIdx.x * 3600;
    for (int idx = threadIdx.x; idx < 3600; idx += blockDim.x) {
        int r = idx / 36, c = idx - r * 36;
        tile[r][c] = ip[idx];
    }
    __syncthreads();
    for (int idx = threadIdx.x; idx < 3600; idx += blockDim.x) {
        int c = idx / 100, r = idx - c * 100;
        op[idx] = tile[r][c];
    }
}

// ---------------------------------------------------------------------------
// One forward + one backward scan pass, in place, on a [B][C][S][L] buffer.
// Cluster of 4 CTAs per batch; CTA `rank` owns output channels [rank*32, +32).
//   S = scan length, L = conv row length, T = positions per warp, NW = warps.
// Weights packed as float2 over ci pairs: wsm[ci2][k][co].{x,y} = w[co][2ci2(+1)][k]
// Prev row staged transposed+padded: pp[j][ci] (row stride 130 floats),
// so a ci-pair at position j is one broadcast LDS.64.
// ---------------------------------------------------------------------------
template <int S, int L, int T, int NW, bool SCR>
__global__ void __launch_bounds__(NW * 32, 1) __cluster_dims__(4, 1, 1)
pass_pair(float* __restrict__ Yext, const float* __restrict__ wA, const float* __restrict__ wB) {
    constexpr int NT    = NW * 32;
    constexpr int PROWS = NW * T + 8;   // padded row count (>= L + 8)
    constexpr int PSTR  = 130;          // floats per pp row (even -> 8B aligned pairs)
    constexpr int SL    = L + 1;
    constexpr int WN    = 64 * 9 * 32;  // float2 weight entries

    extern __shared__ char smraw[];
    u64*   wsm  = (u64*)smraw;                         // [64ci2][9k][32co] packed pairs
    float* pp   = (float*)(smraw + WN * 8);            // [PROWS][PSTR]
    float* sout = pp + PROWS * PSTR;                   // [32co][SL]

    float* Y = SCR ? g_scratch : Yext;

    const int tid    = threadIdx.x;
    const int lane   = tid & 31;
    const int warp   = tid >> 5;
    const int rank   = blockIdx.x & 3;
    const int batch  = blockIdx.x >> 2;
    const int coBase = rank * 32;
    float* Yb = Y + (size_t)batch * Cc * S * L;

    // Zero-fill the padding rows of pp once (never overwritten afterwards).
    for (int idx = tid; idx < PROWS * PSTR; idx += NT) {
        int j = idx / PSTR;
        if (j < 4 || j >= L + 4) pp[idx] = 0.f;   // covers halo + tail rows fully
    }

#pragma unroll 1
    for (int pass = 0; pass < 2; ++pass) {
        const float* wg = pass ? wB : wA;
        // Load + pack weights: global w[co][ci][k] (coalesced) -> wsm pairs.
        for (int idx = tid; idx < 32 * 1152; idx += NT) {
            int c   = idx / 1152;
            int rem = idx - c * 1152;          // rem = ci*9 + k
            int ci  = rem / 9;
            int k   = rem - ci * 9;
            float v = wg[(size_t)(coBase + c) * 1152 + rem];
            ((float*)wsm)[(((ci >> 1) * 9 + k) * 32 + c) * 2 + (ci & 1)] = v;
        }

#pragma unroll 1
        for (int i = 1; i < S; ++i) {
            const int cur  = pass ? (S - 1 - i) : i;
            const int prev = pass ? (S - i)     : (i - 1);

            // Publish our slice of row `prev`, then cluster-sync before reading.
            __threadfence();
            asm volatile("barrier.cluster.arrive.aligned;" ::: "memory");
            asm volatile("barrier.cluster.wait.aligned;" ::: "memory");

            // Stage prev row, transposed: pp[l+4][ci]. Global reads coalesced
            // along l; smem writes stride-130 (2-way conflict max). __ldcg:
            // bypass L1 (peers wrote via L2).
            for (int idx = tid; idx < 128 * L; idx += NT) {
                int ci = idx / L;
                int l  = idx - ci * L;
                pp[(l + 4) * PSTR + ci] = __ldcg(Yb + ((size_t)ci * S + prev) * L + l);
            }
            __syncthreads();

            // Compute: lane = co, warp = strip of T positions. ci packed x2.
            {
                const int l0 = warp * T;
                u64 acc[T];
#pragma unroll
                for (int t = 0; t < T; ++t) acc[t] = 0ull;

                const u64* pc = (const u64*)pp;        // 65 u64 per row
                const u64* wrow = wsm + lane;
#pragma unroll 1
                for (int ci2 = 0; ci2 < 64; ++ci2) {
                    u64 pv[T + 8];
                    const u64* pj = pc + (size_t)l0 * 65 + ci2;
#pragma unroll
                    for (int j = 0; j < T + 8; ++j)
                        pv[j] = pj[j * 65];            // broadcast LDS.64
#pragma unroll
                    for (int k = 0; k < KW; ++k) {
                        u64 wk = wrow[k * 32];         // conflict-free LDS.64
#pragma unroll
                        for (int t = 0; t < T; ++t)
                            FMA2(acc[t], wk, pv[t + k]);
                    }
                    wrow += 9 * 32;
                }
#pragma unroll
                for (int t = 0; t < T; ++t) {
                    int l = l0 + t;
                    if (l < L) sout[lane * SL + l] = fmaxf(f32x2_sum(acc[t]), 0.f);
                }
            }
            __syncthreads();

            // In-place: Y[cur] += relu(conv). Coalesced RMW over own channels.
            for (int idx = tid; idx < 32 * L; idx += NT) {
                int c = idx / L;
                int l = idx - c * L;
                float* g = Yb + ((size_t)(coBase + c) * S + cur) * L + l;
                *g = *g + sout[c * SL + l];
            }
        }
        __threadfence();
    }
}

// ---------------------------------------------------------------------------
extern "C" void kernel_launch(void* const* d_in, const int* in_sizes, int n_in,
                              void* d_out, int out_size) {
    const float* x    = (const float*)d_in[0];
    const float* w_ud = (const float*)d_in[1];
    const float* w_du = (const float*)d_in[2];
    const float* w_lr = (const float*)d_in[3];
    const float* w_rl = (const float*)d_in[4];
    float* Y = (float*)d_out;

    // Vertical: S=36, L=100, T=7, NW=16 (512 thr). PROWS=120.
    // Horizontal: S=100, L=36, T=3, NW=12 (384 thr). PROWS=44.
    constexpr int SMEM_V = 64 * 9 * 32 * 8 + 120 * 130 * 4 + 32 * 101 * 4;  // 222,784 B
    constexpr int SMEM_H = 64 * 9 * 32 * 8 + 44 * 130 * 4 + 32 * 37 * 4;    // 175,072 B

    cudaFuncSetAttribute(pass_pair<36, 100, 7, 16, false>,
                         cudaFuncAttributeMaxDynamicSharedMemorySize, SMEM_V);
    cudaFuncSetAttribute(pass_pair<100, 36, 3, 12, true>,
                         cudaFuncAttributeMaxDynamicSharedMemorySize, SMEM_H);

    copy_k<<<2048, 256>>>((const float4*)x, (float4*)Y, NELEM / 4);

    // Pass 1 (ud, fwd over H) + Pass 2 (du, bwd over H), in place on Y
    pass_pair<36, 100, 7, 16, false><<<128, 512, SMEM_V>>>(Y, w_ud, w_du);

    // [B][C][H][W] -> [B][C][W][H] so the horizontal conv axis is contiguous
    transpose_HW_to_WH<<<Bb * Cc, 256>>>(Y);

    // Pass 3 (lr, fwd over W) + Pass 4 (rl, bwd over W), on g_scratch
    pass_pair<100, 36, 3, 12, true><<<128, 384, SMEM_H>>>(nullptr, w_lr, w_rl);

    // Transpose back into d_out
    transpose_WH_to_HW<<<Bb * Cc, 256>>>(Y);
}